// round 1
// baseline (speedup 1.0000x reference)
#include <cuda_runtime.h>
#include <math.h>

// NeuralNDCG loss, N=4096, no padding (inputs guarantee target in [0,1), pred ~ N(0,1)).
//
// Pipeline:
//   k_B     : B[j] = sum_k |p_j - p_k|  (+ zero colsum buf0)
//   k_idcg  : ideal DCG via rank counting (deterministic block partials)
//   k_build : P_hat = row-softmax(c_i * p_j - B_j), write 64MB matrix,
//             accumulate colsum buf0, zero buf1
//   k_pass  : x49 fused Sinkhorn iteration (col-scale -> block-local row-sum ->
//             row-scale -> write -> accumulate next colsums). One 64MB read +
//             64MB write per iteration. 3-buffer colsum rotation (no memsets).
//   k_last  : iteration 50 fused with DCG contraction (no matrix write)
//   k_final : out = -(dcg / (idcg + 1e-8))

#define NN 4096
#define EPSF 1e-10f
#define ITERS 50
#define PASS_BLOCKS 256
#define PASS_THREADS 512
#define ROWS_PER_BLK (NN / PASS_BLOCKS)   // 16
#define ELEMS_PER_THR (NN / PASS_THREADS) // 8

__device__ float g_mat[(size_t)NN * NN];       // 64 MB scratch (static: no runtime alloc)
__device__ float g_B[NN];
__device__ float g_colsum[3][NN];
__device__ float g_idcgPart[64];
__device__ float g_dcgPart[PASS_BLOCKS];

// ---------- block reductions (512 threads = 16 warps) ----------
__device__ __forceinline__ float bsum512(float v, float* red, int tid) {
    #pragma unroll
    for (int o = 16; o > 0; o >>= 1) v += __shfl_xor_sync(0xffffffffu, v, o);
    __syncthreads();                       // protect red[] from previous use
    if ((tid & 31) == 0) red[tid >> 5] = v;
    __syncthreads();
    if (tid < 32) {
        float r = (tid < 16) ? red[tid] : 0.0f;
        #pragma unroll
        for (int o = 8; o > 0; o >>= 1) r += __shfl_xor_sync(0xffffffffu, r, o);
        if (tid == 0) red[0] = r;
    }
    __syncthreads();
    return red[0];
}

__device__ __forceinline__ float bmax512(float v, float* red, int tid) {
    #pragma unroll
    for (int o = 16; o > 0; o >>= 1) v = fmaxf(v, __shfl_xor_sync(0xffffffffu, v, o));
    __syncthreads();
    if ((tid & 31) == 0) red[tid >> 5] = v;
    __syncthreads();
    if (tid < 32) {
        float r = (tid < 16) ? red[tid] : -INFINITY;
        #pragma unroll
        for (int o = 8; o > 0; o >>= 1) r = fmaxf(r, __shfl_xor_sync(0xffffffffu, r, o));
        if (tid == 0) red[0] = r;
    }
    __syncthreads();
    return red[0];
}

// ---------- B[j] = sum_k |p_j - p_k| ; zero colsum[0] ----------
__global__ void k_B(const float* __restrict__ pred) {
    __shared__ float p_s[NN];
    int tid = threadIdx.x;                 // 64 blocks x 64 threads
    for (int i = tid; i < NN; i += 64) p_s[i] = pred[i];
    __syncthreads();
    int j = blockIdx.x * 64 + tid;
    float pj = p_s[j];
    float a0 = 0.f, a1 = 0.f, a2 = 0.f, a3 = 0.f;
    #pragma unroll 4
    for (int k = 0; k < NN; k += 4) {
        a0 += fabsf(pj - p_s[k + 0]);
        a1 += fabsf(pj - p_s[k + 1]);
        a2 += fabsf(pj - p_s[k + 2]);
        a3 += fabsf(pj - p_s[k + 3]);
    }
    g_B[j] = (a0 + a1) + (a2 + a3);
    g_colsum[0][j] = 0.0f;
}

// ---------- ideal DCG via rank counting ----------
__global__ void k_idcg(const float* __restrict__ target) {
    __shared__ float t_s[NN];
    __shared__ float red2[2];
    int tid = threadIdx.x;                 // 64 blocks x 64 threads
    for (int i = tid; i < NN; i += 64) t_s[i] = target[i];
    __syncthreads();
    int j = blockIdx.x * 64 + tid;
    float tj = t_s[j];
    int r0 = 0, r1 = 0, r2 = 0, r3 = 0;
    #pragma unroll 4
    for (int k = 0; k < NN; k += 4) {
        r0 += (t_s[k + 0] > tj);
        r1 += (t_s[k + 1] > tj);
        r2 += (t_s[k + 2] > tj);
        r3 += (t_s[k + 3] > tj);
    }
    int rank = (r0 + r1) + (r2 + r3);
    float contrib = (exp2f(tj) - 1.0f) / log2f((float)rank + 2.0f);
    #pragma unroll
    for (int o = 16; o > 0; o >>= 1) contrib += __shfl_xor_sync(0xffffffffu, contrib, o);
    if ((tid & 31) == 0) red2[tid >> 5] = contrib;
    __syncthreads();
    if (tid == 0) g_idcgPart[blockIdx.x] = red2[0] + red2[1];
}

// ---------- build P_hat, accumulate colsum[0], zero colsum[1] ----------
__global__ void __launch_bounds__(PASS_THREADS) k_build(const float* __restrict__ pred) {
    __shared__ float p_s[NN];
    __shared__ float B_s[NN];
    __shared__ float red[16];
    int tid = threadIdx.x;
    for (int i = tid; i < NN; i += PASS_THREADS) { p_s[i] = pred[i]; B_s[i] = g_B[i]; }
    __syncthreads();

    int row0 = blockIdx.x * ROWS_PER_BLK;
    float colacc[ELEMS_PER_THR];
    #pragma unroll
    for (int k = 0; k < ELEMS_PER_THR; k++) colacc[k] = 0.0f;

    for (int rr = 0; rr < ROWS_PER_BLK; rr++) {
        int i = row0 + rr;
        float ci = (float)(NN - 1 - 2 * i);
        float v[ELEMS_PER_THR];
        float m = -INFINITY;
        #pragma unroll
        for (int k = 0; k < ELEMS_PER_THR; k++) {
            int j = tid + k * PASS_THREADS;
            v[k] = ci * p_s[j] - B_s[j];
            m = fmaxf(m, v[k]);
        }
        m = bmax512(m, red, tid);
        float z = 0.0f;
        #pragma unroll
        for (int k = 0; k < ELEMS_PER_THR; k++) { v[k] = expf(v[k] - m); z += v[k]; }
        z = bsum512(z, red, tid);
        float invz = 1.0f / z;
        float* rowp = g_mat + (size_t)i * NN;
        #pragma unroll
        for (int k = 0; k < ELEMS_PER_THR; k++) {
            float w = v[k] * invz;
            rowp[tid + k * PASS_THREADS] = w;
            colacc[k] += w;
        }
    }
    #pragma unroll
    for (int k = 0; k < ELEMS_PER_THR; k++)
        atomicAdd(&g_colsum[0][tid + k * PASS_THREADS], colacc[k]);
    if (tid < ROWS_PER_BLK) g_colsum[1][blockIdx.x * ROWS_PER_BLK + tid] = 0.0f;
}

// ---------- one fused Sinkhorn iteration ----------
__global__ void __launch_bounds__(PASS_THREADS) k_pass(int t) {
    __shared__ float c_s[NN];
    __shared__ float red[16];
    const float* __restrict__ prev = g_colsum[(t - 1) % 3];
    float* cur = g_colsum[t % 3];
    float* nxt = g_colsum[(t + 1) % 3];
    int tid = threadIdx.x;
    for (int i = tid; i < NN; i += PASS_THREADS)
        c_s[i] = 1.0f / fmaxf(prev[i], EPSF);
    if (tid < ROWS_PER_BLK) nxt[blockIdx.x * ROWS_PER_BLK + tid] = 0.0f;
    __syncthreads();

    int row0 = blockIdx.x * ROWS_PER_BLK;
    float colacc[ELEMS_PER_THR];
    #pragma unroll
    for (int k = 0; k < ELEMS_PER_THR; k++) colacc[k] = 0.0f;

    for (int rr = 0; rr < ROWS_PER_BLK; rr++) {
        size_t base = (size_t)(row0 + rr) * NN;
        float v[ELEMS_PER_THR];
        float s = 0.0f;
        #pragma unroll
        for (int k = 0; k < ELEMS_PER_THR; k++) {
            int j = tid + k * PASS_THREADS;
            v[k] = g_mat[base + j] * c_s[j];
            s += v[k];
        }
        s = bsum512(s, red, tid);
        float r = 1.0f / fmaxf(s, EPSF);
        #pragma unroll
        for (int k = 0; k < ELEMS_PER_THR; k++) {
            float w = v[k] * r;
            g_mat[base + tid + k * PASS_THREADS] = w;
            colacc[k] += w;
        }
    }
    #pragma unroll
    for (int k = 0; k < ELEMS_PER_THR; k++)
        atomicAdd(&cur[tid + k * PASS_THREADS], colacc[k]);
}

// ---------- last iteration fused with DCG contraction ----------
__global__ void __launch_bounds__(PASS_THREADS) k_last(int t, const float* __restrict__ target) {
    __shared__ float c_s[NN];
    __shared__ float g_s[NN];
    __shared__ float red[16];
    const float* __restrict__ prev = g_colsum[(t - 1) % 3];
    int tid = threadIdx.x;
    for (int i = tid; i < NN; i += PASS_THREADS) {
        c_s[i] = 1.0f / fmaxf(prev[i], EPSF);
        g_s[i] = exp2f(target[i]) - 1.0f;
    }
    __syncthreads();

    int row0 = blockIdx.x * ROWS_PER_BLK;
    float acc = 0.0f;  // valid on tid 0 only
    for (int rr = 0; rr < ROWS_PER_BLK; rr++) {
        int i = row0 + rr;
        size_t base = (size_t)i * NN;
        float v[ELEMS_PER_THR];
        float s = 0.0f;
        #pragma unroll
        for (int k = 0; k < ELEMS_PER_THR; k++) {
            int j = tid + k * PASS_THREADS;
            v[k] = g_mat[base + j] * c_s[j];
            s += v[k];
        }
        s = bsum512(s, red, tid);
        float r = 1.0f / fmaxf(s, EPSF);
        float d = 0.0f;
        #pragma unroll
        for (int k = 0; k < ELEMS_PER_THR; k++)
            d += v[k] * g_s[tid + k * PASS_THREADS];
        d = bsum512(d, red, tid);
        if (tid == 0) acc += (d * r) / log2f((float)i + 2.0f);
    }
    if (tid == 0) g_dcgPart[blockIdx.x] = acc;
}

// ---------- final scalar (deterministic sequential reduce) ----------
__global__ void k_final(float* __restrict__ out) {
    if (threadIdx.x == 0) {
        float dcg = 0.0f;
        for (int i = 0; i < PASS_BLOCKS; i++) dcg += g_dcgPart[i];
        float idcg = 0.0f;
        for (int i = 0; i < 64; i++) idcg += g_idcgPart[i];
        out[0] = -(dcg / (idcg + 1e-8f));
    }
}

extern "C" void kernel_launch(void* const* d_in, const int* in_sizes, int n_in,
                              void* d_out, int out_size) {
    const float* pred   = (const float*)d_in[0];
    const float* target = (const float*)d_in[1];
    float* out = (float*)d_out;

    k_B<<<64, 64>>>(pred);
    k_idcg<<<64, 64>>>(target);
    k_build<<<PASS_BLOCKS, PASS_THREADS>>>(pred);
    for (int t = 1; t < ITERS; t++)
        k_pass<<<PASS_BLOCKS, PASS_THREADS>>>(t);
    k_last<<<PASS_BLOCKS, PASS_THREADS>>>(ITERS, target);
    k_final<<<1, 32>>>(out);
}